// round 3
// baseline (speedup 1.0000x reference)
#include <cuda_runtime.h>
#include <cuda_bf16.h>
#include <cstdint>

#define NIMG 16
#define NBOX 16128
#define NCH  85
#define KSEL 500
#define KPAD 512
#define NCB  16            // 512 / 32 column blocks
#define SIG_NEG4 0.017986210f   // sigmoid(-4) for zero-overlap pairs

// ---------------- device scratch (no allocations allowed) ----------------
__device__ unsigned g_sbits[NIMG * NBOX];                 // packed score bits
__device__ float    g_s[NIMG][KPAD];                      // sorted top scores
__device__ float4   g_box[NIMG][KPAD];                    // gathered boxes
__device__ float    g_y[NIMG][KPAD];                      // gathered targets
__device__ float    g_p[(size_t)NIMG * NCB * KPAD * 32];  // prune, [img][cb][i][t]
__device__ float    g_tri[NIMG][NCB][4][32];              // diag 8x8 triangles
__device__ float    g_E[NIMG][KPAD];                      // exp(20*v)
__device__ float    g_yE[NIMG][KPAD];                     // y * exp(20*v)
__device__ float    g_c[NIMG][KPAD];                      // prec*y per row

__constant__ unsigned char c_tk[28] = {1,2,2,3,3,3,4,4,4,4,5,5,5,5,5,
                                       6,6,6,6,6,6,7,7,7,7,7,7,7};
__constant__ unsigned char c_tj[28] = {0,0,1,0,1,2,0,1,2,3,0,1,2,3,4,
                                       0,1,2,3,4,5,0,1,2,3,4,5,6};

__device__ __forceinline__ float frcp(float x) {
    float r; asm("rcp.approx.f32 %0, %1;" : "=f"(r) : "f"(x)); return r;
}

// ---------------- K1: scores = max over channels 1..84 ----------------
__global__ __launch_bounds__(128) void k_scores(const float* __restrict__ preds) {
    __shared__ __align__(16) float sh[128 * NCH];
    int img = blockIdx.x / 126;
    int ch  = blockIdx.x % 126;
    size_t base = ((size_t)img * NBOX + (size_t)ch * 128) * NCH;
    const float4* src = reinterpret_cast<const float4*>(preds + base);
    float4* dst = reinterpret_cast<float4*>(sh);
    #pragma unroll 8
    for (int u = threadIdx.x; u < 128 * NCH / 4; u += 128) dst[u] = src[u];
    __syncthreads();
    int r = threadIdx.x;
    float m = sh[r * NCH + 1];
    #pragma unroll
    for (int c = 2; c < NCH; ++c) m = fmaxf(m, sh[r * NCH + c]);
    g_sbits[(size_t)img * NBOX + ch * 128 + r] = __float_as_uint(m);
}

// ---------------- K2: per-image radix select (4x8-bit) + bitonic ----------------
__global__ __launch_bounds__(512) void k_select(const float4* __restrict__ boxes,
                                                const int* __restrict__ tgt) {
    const int img = blockIdx.x;
    const int tid = threadIdx.x;
    const int w = tid >> 5, lane = tid & 31;
    __shared__ unsigned whist[16 * 256];
    __shared__ unsigned hist[256];
    __shared__ unsigned wtot[16];
    __shared__ unsigned s_bin, s_rem, s_cnt;
    __shared__ unsigned long long sbuf[1024];
    const unsigned* sb = g_sbits + (size_t)img * NBOX;

    unsigned prefix = 0;
    unsigned target = KSEL;

    #pragma unroll
    for (int pass = 0; pass < 4; ++pass) {
        const int shift = 24 - pass * 8;
        for (int u = tid; u < 4096; u += 512) whist[u] = 0;
        __syncthreads();
        for (int j = tid; j < NBOX; j += 512) {
            unsigned bits = sb[j];
            bool ok = (pass == 0) || ((bits >> (shift + 8)) == prefix);
            unsigned act = __ballot_sync(0xFFFFFFFFu, ok);
            if (ok) {
                unsigned bin = (bits >> shift) & 255u;
                unsigned mask = __match_any_sync(act, bin);
                if ((mask & ((1u << lane) - 1u)) == 0)
                    whist[w * 256 + bin] += __popc(mask);
            }
        }
        __syncthreads();
        if (tid < 256) {
            unsigned h = 0;
            #pragma unroll
            for (int ww = 0; ww < 16; ++ww) h += whist[ww * 256 + tid];
            hist[tid] = h;
        }
        __syncthreads();
        unsigned x0 = (tid < 256) ? hist[255 - tid] : 0u;
        unsigned x = x0;
        #pragma unroll
        for (int off = 1; off < 32; off <<= 1) {
            unsigned yv = __shfl_up_sync(0xFFFFFFFFu, x, off);
            if (lane >= off) x += yv;
        }
        if (lane == 31) wtot[w] = x;
        __syncthreads();
        unsigned add = 0;
        #pragma unroll
        for (int ww = 0; ww < 8; ++ww) if (ww < w) add += wtot[ww];
        unsigned inc = x + add;
        if (tid < 256 && inc >= target && (inc - x0) < target) {
            s_bin = 255u - (unsigned)tid;
            s_rem = target - (inc - x0);
        }
        __syncthreads();
        prefix = (prefix << 8) | s_bin;
        target = s_rem;
        __syncthreads();
    }
    const unsigned T = prefix;

    for (int u = tid; u < 1024; u += 512) sbuf[u] = ~0ULL;
    if (tid == 0) s_cnt = 0;
    __syncthreads();
    for (int j = tid; j < NBOX; j += 512) {
        unsigned bits = sb[j];
        if (bits >= T) {
            unsigned p = atomicAdd(&s_cnt, 1);
            if (p < 1024)
                sbuf[p] = ~(((unsigned long long)bits << 32) |
                            (unsigned long long)(0xFFFFFFFFu - (unsigned)j));
        }
    }
    __syncthreads();

    for (unsigned kk = 2; kk <= 1024; kk <<= 1) {
        for (unsigned st = kk >> 1; st > 0; st >>= 1) {
            unsigned t = (unsigned)tid;
            unsigned i = ((t & ~(st - 1)) << 1) | (t & (st - 1));
            unsigned j2 = i | st;
            bool up = ((i & kk) == 0);
            unsigned long long a = sbuf[i], b = sbuf[j2];
            if ((a > b) == up) { sbuf[i] = b; sbuf[j2] = a; }
            __syncthreads();
        }
    }

    if (tid < KSEL) {
        unsigned long long key = ~sbuf[tid];
        unsigned bits = (unsigned)(key >> 32);
        unsigned idx  = 0xFFFFFFFFu - (unsigned)(key & 0xFFFFFFFFull);
        g_s[img][tid] = __uint_as_float(bits);
        g_box[img][tid] = boxes[(size_t)img * NBOX + idx];
        g_y[img][tid] = (float)tgt[(size_t)img * NBOX + idx];
    } else {
        g_s[img][tid] = 0.f;
        g_box[img][tid] = make_float4(0.f, 0.f, 0.f, 0.f);
        g_y[img][tid] = 0.f;
    }
}

// ---------------- K3: prune matrix, triangle tiles only ----------------
// grid (34, NIMG) x 128: 4 warps/block, one 32x32 tile per warp, 136 tiles/img.
__global__ __launch_bounds__(128) void k_prune() {
    const int img = blockIdx.y;
    const int w = threadIdx.x >> 5, lane = threadIdx.x & 31;
    const int t = blockIdx.x * 4 + w;                 // tile id, 0..135
    __shared__ float4 sbj[4][32];
    __shared__ float  saj[4][32];
    __shared__ float  sdiag[4][32][32];               // staged diag tiles

    // tile -> (rb, cb)
    int rb = (int)((sqrtf(8.f * (float)t + 1.f) - 1.f) * 0.5f);
    if ((rb + 1) * (rb + 2) / 2 <= t) rb++;
    if (rb * (rb + 1) / 2 > t) rb--;
    const int cb = t - rb * (rb + 1) / 2;

    // column boxes for this tile
    {
        float4 b = g_box[img][cb * 32 + lane];
        sbj[w][lane] = b;
        saj[w][lane] = fmaxf(b.z - b.x, 0.f) * fmaxf(b.w - b.y, 0.f);
    }
    __syncwarp();

    const int i = rb * 32 + lane;
    float4 bi = g_box[img][i];
    float ai = fmaxf(bi.z - bi.x, 0.f) * fmaxf(bi.w - bi.y, 0.f);
    float out[32];
    #pragma unroll
    for (int c = 0; c < 32; ++c) {
        float4 bb = sbj[w][c];
        float iw = fminf(bi.z, bb.z) - fmaxf(bi.x, bb.x);
        float ih = fminf(bi.w, bb.w) - fmaxf(bi.y, bb.y);
        bool ov = (iw > 0.f) && (ih > 0.f);
        float p;
        if (__any_sync(0xFFFFFFFFu, ov)) {
            float inter = fmaxf(iw, 0.f) * fmaxf(ih, 0.f);
            float uni = ai + saj[w][c] - inter;
            float iou = inter * frcp(fmaxf(uni, 1e-9f));
            p = frcp(1.f + __expf((0.4f - iou) * 10.f));
        } else {
            p = SIG_NEG4;
        }
        out[c] = p;
    }
    // store strip
    float4* dst = reinterpret_cast<float4*>(
        &g_p[(((size_t)img * NCB + cb) * KPAD + i) * 32]);
    #pragma unroll
    for (int u = 0; u < 8; ++u) dst[u] = reinterpret_cast<float4*>(out)[u];

    // diag tiles: extract 8x8 sub-block triangles for k_nms
    if (rb == cb) {
        #pragma unroll
        for (int c = 0; c < 32; ++c) sdiag[w][lane][c] = out[c];
        __syncwarp();
        for (int e = lane; e < 112; e += 32) {
            int q = e / 28, rem = e - q * 28;
            int k = c_tk[rem], j = c_tj[rem];
            g_tri[img][cb][q][rem] = sdiag[w][q * 8 + k][q * 8 + j];
        }
    }
}

// ---------------- K4: soft-NMS — 8-col speculative sub-blocks ----------------
__global__ __launch_bounds__(512) void k_nms() {
    const int img = blockIdx.x;
    const int tid = threadIdx.x;
    const int w = tid >> 5, lane = tid & 31;
    __shared__ __align__(16) float vsh[KPAD];
    __shared__ float tri[NCB][4][32];

    for (int u = tid; u < NCB * 4 * 32; u += 512)
        reinterpret_cast<float*>(tri)[u] =
            reinterpret_cast<const float*>(g_tri)[img * (NCB * 4 * 32) + u];

    float r = g_s[img][tid];
    const float4* pb = reinterpret_cast<const float4*>(g_p) +
                       ((size_t)img * NCB * KPAD + tid) * 8;
    float4 cur[8], nxt[8];
    #pragma unroll
    for (int u = 0; u < 8; ++u) cur[u] = pb[u];
    __syncthreads();

    for (int cb = 0; cb < NCB; ++cb) {
        if (cb < NCB - 1 && w >= cb + 1) {
            const float4* nb = pb + (size_t)(cb + 1) * KPAD * 8;
            #pragma unroll
            for (int u = 0; u < 8; ++u) nxt[u] = nb[u];
        }
        float pc[32];
        #pragma unroll
        for (int u = 0; u < 8; ++u) {
            pc[4*u+0] = cur[u].x; pc[4*u+1] = cur[u].y;
            pc[4*u+2] = cur[u].z; pc[4*u+3] = cur[u].w;
        }
        if (w == cb) {
            #pragma unroll
            for (int q = 0; q < 4; ++q) {
                const int base = q * 8;
                const float* tq = &tri[cb][q][0];
                float a0 = __shfl_sync(0xFFFFFFFFu, r, base + 0);
                float a1 = __shfl_sync(0xFFFFFFFFu, r, base + 1);
                float a2 = __shfl_sync(0xFFFFFFFFu, r, base + 2);
                float a3 = __shfl_sync(0xFFFFFFFFu, r, base + 3);
                float a4 = __shfl_sync(0xFFFFFFFFu, r, base + 4);
                float a5 = __shfl_sync(0xFFFFFFFFu, r, base + 5);
                float a6 = __shfl_sync(0xFFFFFFFFu, r, base + 6);
                float a7 = __shfl_sync(0xFFFFFFFFu, r, base + 7);
                float v0 = fmaxf(a0, 0.f);
                a1 = fmaf(-tq[0], v0, a1);  float v1 = fmaxf(a1, 0.f);
                a2 = fmaf(-tq[1], v0, a2);  a2 = fmaf(-tq[2], v1, a2);
                float v2 = fmaxf(a2, 0.f);
                a3 = fmaf(-tq[3], v0, a3);  a3 = fmaf(-tq[4], v1, a3);
                a3 = fmaf(-tq[5], v2, a3);  float v3 = fmaxf(a3, 0.f);
                a4 = fmaf(-tq[6], v0, a4);  a4 = fmaf(-tq[7], v1, a4);
                a4 = fmaf(-tq[8], v2, a4);  a4 = fmaf(-tq[9], v3, a4);
                float v4 = fmaxf(a4, 0.f);
                a5 = fmaf(-tq[10], v0, a5); a5 = fmaf(-tq[11], v1, a5);
                a5 = fmaf(-tq[12], v2, a5); a5 = fmaf(-tq[13], v3, a5);
                a5 = fmaf(-tq[14], v4, a5); float v5 = fmaxf(a5, 0.f);
                a6 = fmaf(-tq[15], v0, a6); a6 = fmaf(-tq[16], v1, a6);
                a6 = fmaf(-tq[17], v2, a6); a6 = fmaf(-tq[18], v3, a6);
                a6 = fmaf(-tq[19], v4, a6); a6 = fmaf(-tq[20], v5, a6);
                float v6 = fmaxf(a6, 0.f);
                a7 = fmaf(-tq[21], v0, a7); a7 = fmaf(-tq[22], v1, a7);
                a7 = fmaf(-tq[23], v2, a7); a7 = fmaf(-tq[24], v3, a7);
                a7 = fmaf(-tq[25], v4, a7); a7 = fmaf(-tq[26], v5, a7);
                a7 = fmaf(-tq[27], v6, a7); float v7 = fmaxf(a7, 0.f);
                if (lane == base + 0) vsh[tid] = v0;
                if (lane == base + 1) vsh[tid] = v1;
                if (lane == base + 2) vsh[tid] = v2;
                if (lane == base + 3) vsh[tid] = v3;
                if (lane == base + 4) vsh[tid] = v4;
                if (lane == base + 5) vsh[tid] = v5;
                if (lane == base + 6) vsh[tid] = v6;
                if (lane == base + 7) vsh[tid] = v7;
                float m01 = pc[base + 0] * v0; m01 = fmaf(pc[base + 1], v1, m01);
                float m23 = pc[base + 2] * v2; m23 = fmaf(pc[base + 3], v3, m23);
                float m45 = pc[base + 4] * v4; m45 = fmaf(pc[base + 5], v5, m45);
                float m67 = pc[base + 6] * v6; m67 = fmaf(pc[base + 7], v7, m67);
                r = r - ((m01 + m23) + (m45 + m67));
            }
        }
        __syncthreads();
        if (w > cb) {
            const float4* vv = reinterpret_cast<const float4*>(&vsh[cb * 32]);
            float4 x0 = vv[0], x1 = vv[1], x2 = vv[2], x3 = vv[3];
            float4 x4 = vv[4], x5 = vv[5], x6 = vv[6], x7 = vv[7];
            float b0 = pc[0] * x0.x;  b0 = fmaf(pc[1], x0.y, b0);
            b0 = fmaf(pc[2], x0.z, b0);  b0 = fmaf(pc[3], x0.w, b0);
            float b1 = pc[4] * x1.x;  b1 = fmaf(pc[5], x1.y, b1);
            b1 = fmaf(pc[6], x1.z, b1);  b1 = fmaf(pc[7], x1.w, b1);
            float b2 = pc[8] * x2.x;  b2 = fmaf(pc[9], x2.y, b2);
            b2 = fmaf(pc[10], x2.z, b2); b2 = fmaf(pc[11], x2.w, b2);
            float b3 = pc[12] * x3.x; b3 = fmaf(pc[13], x3.y, b3);
            b3 = fmaf(pc[14], x3.z, b3); b3 = fmaf(pc[15], x3.w, b3);
            b0 = fmaf(pc[16], x4.x, b0); b0 = fmaf(pc[17], x4.y, b0);
            b0 = fmaf(pc[18], x4.z, b0); b0 = fmaf(pc[19], x4.w, b0);
            b1 = fmaf(pc[20], x5.x, b1); b1 = fmaf(pc[21], x5.y, b1);
            b1 = fmaf(pc[22], x5.z, b1); b1 = fmaf(pc[23], x5.w, b1);
            b2 = fmaf(pc[24], x6.x, b2); b2 = fmaf(pc[25], x6.y, b2);
            b2 = fmaf(pc[26], x6.z, b2); b2 = fmaf(pc[27], x6.w, b2);
            b3 = fmaf(pc[28], x7.x, b3); b3 = fmaf(pc[29], x7.y, b3);
            b3 = fmaf(pc[30], x7.z, b3); b3 = fmaf(pc[31], x7.w, b3);
            r = r - ((b0 + b1) + (b2 + b3));
        }
        #pragma unroll
        for (int u = 0; u < 8; ++u) cur[u] = nxt[u];
    }
    __syncthreads();
    float v = vsh[tid];
    float E = __expf(20.f * v);
    bool valid = tid < KSEL;
    g_E[img][tid]  = valid ? E : 0.f;
    g_yE[img][tid] = valid ? g_y[img][tid] * E : 0.f;
}

// ---------------- K5: ap_loss, 32 rows x 4 col-chunks per block ----------------
__global__ __launch_bounds__(128) void k_ap() {
    const int img = blockIdx.y;
    const int rb = blockIdx.x;
    const int c = threadIdx.x >> 5, lane = threadIdx.x & 31;
    const int row = rb * 32 + lane;
    __shared__ float Es[KPAD], yEs[KPAD];
    __shared__ float rsh[4][32], rshy[4][32];
    for (int u = threadIdx.x; u < KPAD; u += 128) {
        Es[u]  = g_E[img][u];
        yEs[u] = g_yE[img][u];
    }
    __syncthreads();
    float Ei = Es[row];
    float sh = 0.f, shy = 0.f;
    const int j0 = c * 125;
    #pragma unroll 5
    for (int j = j0; j < j0 + 125; ++j) {
        float ej = Es[j];
        float rr = frcp(Ei + ej);
        sh  = fmaf(ej, rr, sh);
        shy = fmaf(yEs[j], rr, shy);
    }
    rsh[c][lane] = sh; rshy[c][lane] = shy;
    __syncthreads();
    if (c == 0) {
        float S  = rsh[0][lane] + rsh[1][lane] + rsh[2][lane] + rsh[3][lane];
        float Sy = rshy[0][lane] + rshy[1][lane] + rshy[2][lane] + rshy[3][lane];
        // diagonal term contributed ~0.5 exactly; fold into the +1 offsets
        float ci = 0.f;
        float yi = g_y[img][row];
        if (row < KSEL && yi != 0.f)
            ci = __fdividef(0.5f + Sy, 0.5f + S);
        g_c[img][row] = ci;
    }
}

// ---------------- K6: warp-per-image final reduction ----------------
__global__ __launch_bounds__(512) void k_final(float* __restrict__ out) {
    const int w = threadIdx.x >> 5, lane = threadIdx.x & 31;
    __shared__ float part[16];
    float sc = 0.f, sy = 0.f;
    #pragma unroll
    for (int u = lane; u < KPAD; u += 32) {
        sc += g_c[w][u];
        sy += g_y[w][u];
    }
    #pragma unroll
    for (int off = 16; off > 0; off >>= 1) {
        sc += __shfl_down_sync(0xFFFFFFFFu, sc, off);
        sy += __shfl_down_sync(0xFFFFFFFFu, sy, off);
    }
    if (lane == 0) part[w] = 1.f - sc / fmaxf(sy, 1.f);
    __syncthreads();
    if (threadIdx.x == 0) {
        float t = 0.f;
        #pragma unroll
        for (int k = 0; k < NIMG; ++k) t += part[k];
        out[0] = t / (float)NIMG;
    }
}

// ---------------- driver ----------------
extern "C" void kernel_launch(void* const* d_in, const int* in_sizes, int n_in,
                              void* d_out, int out_size) {
    const float* preds = nullptr;
    const float* boxes = nullptr;
    const int*   targets = nullptr;
    for (int i = 0; i < n_in; ++i) {
        long sz = in_sizes[i];
        if (sz == (long)NIMG * NBOX * NCH) preds = (const float*)d_in[i];
        else if (sz == (long)NIMG * NBOX * 4) boxes = (const float*)d_in[i];
        else if (sz == (long)NIMG * NBOX) targets = (const int*)d_in[i];
    }
    if (!preds)   preds   = (const float*)d_in[0];
    if (!boxes)   boxes   = (const float*)d_in[1];
    if (!targets) targets = (const int*)d_in[2];

    k_scores<<<NIMG * 126, 128>>>(preds);
    k_select<<<NIMG, 512>>>(reinterpret_cast<const float4*>(boxes), targets);
    k_prune<<<dim3(34, NIMG), 128>>>();
    k_nms<<<NIMG, 512>>>();
    k_ap<<<dim3(16, NIMG), 128>>>();
    k_final<<<1, 512>>>((float*)d_out);
}

// round 4
// speedup vs baseline: 1.0150x; 1.0150x over previous
#include <cuda_runtime.h>
#include <cuda_bf16.h>
#include <cstdint>

#define NIMG 16
#define NBOX 16128
#define NCH  85
#define KSEL 500
#define KPAD 512
#define NCB  16            // 512 / 32 column blocks
#define SIG_NEG4 0.017986210f   // sigmoid(-4) for zero-overlap pairs

// ---------------- device scratch (no allocations allowed) ----------------
__device__ unsigned g_sbits[NIMG * NBOX];                 // packed score bits
__device__ float    g_s[NIMG][KPAD];                      // sorted top scores
__device__ float4   g_box[NIMG][KPAD];                    // gathered boxes
__device__ float    g_y[NIMG][KPAD];                      // gathered targets
__device__ float    g_p[(size_t)NIMG * NCB * KPAD * 32];  // prune, [img][cb][i][t]
__device__ float    g_tri[NIMG][NCB][4][32];              // diag 8x8 triangles
__device__ float    g_E[NIMG][KPAD];                      // exp(20*v)
__device__ float    g_yE[NIMG][KPAD];                     // y * exp(20*v)
__device__ float    g_c[NIMG][KPAD];                      // prec*y per row

__constant__ unsigned char c_tk[28] = {1,2,2,3,3,3,4,4,4,4,5,5,5,5,5,
                                       6,6,6,6,6,6,7,7,7,7,7,7,7};
__constant__ unsigned char c_tj[28] = {0,0,1,0,1,2,0,1,2,3,0,1,2,3,4,
                                       0,1,2,3,4,5,0,1,2,3,4,5,6};

__device__ __forceinline__ float frcp(float x) {
    float r; asm("rcp.approx.f32 %0, %1;" : "=f"(r) : "f"(x)); return r;
}

// ---------------- K1: scores = max over channels 1..84 ----------------
__global__ __launch_bounds__(128) void k_scores(const float* __restrict__ preds) {
    __shared__ __align__(16) float sh[128 * NCH];
    int img = blockIdx.x / 126;
    int ch  = blockIdx.x % 126;
    size_t base = ((size_t)img * NBOX + (size_t)ch * 128) * NCH;
    const float4* src = reinterpret_cast<const float4*>(preds + base);
    float4* dst = reinterpret_cast<float4*>(sh);
    #pragma unroll 8
    for (int u = threadIdx.x; u < 128 * NCH / 4; u += 128) dst[u] = src[u];
    __syncthreads();
    int r = threadIdx.x;
    float m = sh[r * NCH + 1];
    #pragma unroll
    for (int c = 2; c < NCH; ++c) m = fmaxf(m, sh[r * NCH + c]);
    g_sbits[(size_t)img * NBOX + ch * 128 + r] = __float_as_uint(m);
}

// ---------------- K2: per-image radix select (4x8-bit) + bitonic ----------------
__global__ __launch_bounds__(512) void k_select(const float4* __restrict__ boxes,
                                                const int* __restrict__ tgt) {
    const int img = blockIdx.x;
    const int tid = threadIdx.x;
    const int w = tid >> 5, lane = tid & 31;
    __shared__ unsigned whist[16 * 256];
    __shared__ unsigned hist[256];
    __shared__ unsigned wtot[16];
    __shared__ unsigned s_bin, s_rem, s_cnt;
    __shared__ unsigned long long sbuf[1024];
    const unsigned* sb = g_sbits + (size_t)img * NBOX;

    unsigned prefix = 0;
    unsigned target = KSEL;

    #pragma unroll
    for (int pass = 0; pass < 4; ++pass) {
        const int shift = 24 - pass * 8;
        for (int u = tid; u < 4096; u += 512) whist[u] = 0;
        __syncthreads();
        for (int j = tid; j < NBOX; j += 512) {
            unsigned bits = sb[j];
            bool ok = (pass == 0) || ((bits >> (shift + 8)) == prefix);
            unsigned act = __ballot_sync(0xFFFFFFFFu, ok);
            if (ok) {
                unsigned bin = (bits >> shift) & 255u;
                unsigned mask = __match_any_sync(act, bin);
                if ((mask & ((1u << lane) - 1u)) == 0)
                    whist[w * 256 + bin] += __popc(mask);
            }
        }
        __syncthreads();
        if (tid < 256) {
            unsigned h = 0;
            #pragma unroll
            for (int ww = 0; ww < 16; ++ww) h += whist[ww * 256 + tid];
            hist[tid] = h;
        }
        __syncthreads();
        unsigned x0 = (tid < 256) ? hist[255 - tid] : 0u;
        unsigned x = x0;
        #pragma unroll
        for (int off = 1; off < 32; off <<= 1) {
            unsigned yv = __shfl_up_sync(0xFFFFFFFFu, x, off);
            if (lane >= off) x += yv;
        }
        if (lane == 31) wtot[w] = x;
        __syncthreads();
        unsigned add = 0;
        #pragma unroll
        for (int ww = 0; ww < 8; ++ww) if (ww < w) add += wtot[ww];
        unsigned inc = x + add;
        if (tid < 256 && inc >= target && (inc - x0) < target) {
            s_bin = 255u - (unsigned)tid;
            s_rem = target - (inc - x0);
        }
        __syncthreads();
        prefix = (prefix << 8) | s_bin;
        target = s_rem;
        __syncthreads();
    }
    const unsigned T = prefix;

    for (int u = tid; u < 1024; u += 512) sbuf[u] = ~0ULL;
    if (tid == 0) s_cnt = 0;
    __syncthreads();
    for (int j = tid; j < NBOX; j += 512) {
        unsigned bits = sb[j];
        if (bits >= T) {
            unsigned p = atomicAdd(&s_cnt, 1);
            if (p < 1024)
                sbuf[p] = ~(((unsigned long long)bits << 32) |
                            (unsigned long long)(0xFFFFFFFFu - (unsigned)j));
        }
    }
    __syncthreads();

    for (unsigned kk = 2; kk <= 1024; kk <<= 1) {
        for (unsigned st = kk >> 1; st > 0; st >>= 1) {
            unsigned t = (unsigned)tid;
            unsigned i = ((t & ~(st - 1)) << 1) | (t & (st - 1));
            unsigned j2 = i | st;
            bool up = ((i & kk) == 0);
            unsigned long long a = sbuf[i], b = sbuf[j2];
            if ((a > b) == up) { sbuf[i] = b; sbuf[j2] = a; }
            __syncthreads();
        }
    }

    if (tid < KSEL) {
        unsigned long long key = ~sbuf[tid];
        unsigned bits = (unsigned)(key >> 32);
        unsigned idx  = 0xFFFFFFFFu - (unsigned)(key & 0xFFFFFFFFull);
        g_s[img][tid] = __uint_as_float(bits);
        g_box[img][tid] = boxes[(size_t)img * NBOX + idx];
        g_y[img][tid] = (float)tgt[(size_t)img * NBOX + idx];
    } else {
        g_s[img][tid] = 0.f;
        g_box[img][tid] = make_float4(0.f, 0.f, 0.f, 0.f);
        g_y[img][tid] = 0.f;
    }
}

// ---------------- K3: prune matrix, triangle tiles only ----------------
__global__ __launch_bounds__(128) void k_prune() {
    const int img = blockIdx.y;
    const int w = threadIdx.x >> 5, lane = threadIdx.x & 31;
    const int t = blockIdx.x * 4 + w;                 // tile id, 0..135
    __shared__ float4 sbj[4][32];
    __shared__ float  saj[4][32];
    __shared__ float  sdiag[4][32][32];

    int rb = (int)((sqrtf(8.f * (float)t + 1.f) - 1.f) * 0.5f);
    if ((rb + 1) * (rb + 2) / 2 <= t) rb++;
    if (rb * (rb + 1) / 2 > t) rb--;
    const int cb = t - rb * (rb + 1) / 2;

    {
        float4 b = g_box[img][cb * 32 + lane];
        sbj[w][lane] = b;
        saj[w][lane] = fmaxf(b.z - b.x, 0.f) * fmaxf(b.w - b.y, 0.f);
    }
    __syncwarp();

    const int i = rb * 32 + lane;
    float4 bi = g_box[img][i];
    float ai = fmaxf(bi.z - bi.x, 0.f) * fmaxf(bi.w - bi.y, 0.f);
    float out[32];
    #pragma unroll
    for (int c = 0; c < 32; ++c) {
        float4 bb = sbj[w][c];
        float iw = fminf(bi.z, bb.z) - fmaxf(bi.x, bb.x);
        float ih = fminf(bi.w, bb.w) - fmaxf(bi.y, bb.y);
        bool ov = (iw > 0.f) && (ih > 0.f);
        float p;
        if (__any_sync(0xFFFFFFFFu, ov)) {
            float inter = fmaxf(iw, 0.f) * fmaxf(ih, 0.f);
            float uni = ai + saj[w][c] - inter;
            float iou = inter * frcp(fmaxf(uni, 1e-9f));
            p = frcp(1.f + __expf((0.4f - iou) * 10.f));
        } else {
            p = SIG_NEG4;
        }
        out[c] = p;
    }
    float4* dst = reinterpret_cast<float4*>(
        &g_p[(((size_t)img * NCB + cb) * KPAD + i) * 32]);
    #pragma unroll
    for (int u = 0; u < 8; ++u) dst[u] = reinterpret_cast<float4*>(out)[u];

    if (rb == cb) {
        #pragma unroll
        for (int c = 0; c < 32; ++c) sdiag[w][lane][c] = out[c];
        __syncwarp();
        for (int e = lane; e < 112; e += 32) {
            int q = e / 28, rem = e - q * 28;
            int k = c_tk[rem], j = c_tj[rem];
            g_tri[img][cb][q][rem] = sdiag[w][q * 8 + k][q * 8 + j];
        }
    }
}

// ---------------- K4: soft-NMS — dataflow-pipelined, no inner barriers ----------------
__global__ __launch_bounds__(512) void k_nms() {
    const int img = blockIdx.x;
    const int tid = threadIdx.x;
    const int w = tid >> 5, lane = tid & 31;
    __shared__ __align__(16) float vsh[KPAD];
    __shared__ float tri[NCB][4][32];
    __shared__ volatile int flag[NCB];

    for (int u = tid; u < NCB * 4 * 32; u += 512)
        reinterpret_cast<float*>(tri)[u] =
            reinterpret_cast<const float*>(g_tri)[img * (NCB * 4 * 32) + u];
    if (tid < NCB) flag[tid] = 0;

    float r = g_s[img][tid];
    const float4* pb = reinterpret_cast<const float4*>(g_p) +
                       ((size_t)img * NCB * KPAD + tid) * 8;
    __syncthreads();

    float4 cur[8], nxt[8];
    #pragma unroll
    for (int u = 0; u < 8; ++u) cur[u] = pb[u];     // tile 0 (diag for w==0)

    // consume column blocks 0..w-1 as their v's become available
    for (int cb = 0; cb < w; ++cb) {
        const float4* nb = pb + (size_t)(cb + 1) * KPAD * 8;   // next tile (<= diag)
        #pragma unroll
        for (int u = 0; u < 8; ++u) nxt[u] = nb[u];
        while (flag[cb] == 0) { }
        __threadfence_block();
        const float4* vv = reinterpret_cast<const float4*>(&vsh[cb * 32]);
        float4 x0 = vv[0], x1 = vv[1], x2 = vv[2], x3 = vv[3];
        float4 x4 = vv[4], x5 = vv[5], x6 = vv[6], x7 = vv[7];
        float b0 = cur[0].x * x0.x;   b0 = fmaf(cur[0].y, x0.y, b0);
        b0 = fmaf(cur[0].z, x0.z, b0); b0 = fmaf(cur[0].w, x0.w, b0);
        float b1 = cur[1].x * x1.x;   b1 = fmaf(cur[1].y, x1.y, b1);
        b1 = fmaf(cur[1].z, x1.z, b1); b1 = fmaf(cur[1].w, x1.w, b1);
        float b2 = cur[2].x * x2.x;   b2 = fmaf(cur[2].y, x2.y, b2);
        b2 = fmaf(cur[2].z, x2.z, b2); b2 = fmaf(cur[2].w, x2.w, b2);
        float b3 = cur[3].x * x3.x;   b3 = fmaf(cur[3].y, x3.y, b3);
        b3 = fmaf(cur[3].z, x3.z, b3); b3 = fmaf(cur[3].w, x3.w, b3);
        b0 = fmaf(cur[4].x, x4.x, b0); b0 = fmaf(cur[4].y, x4.y, b0);
        b0 = fmaf(cur[4].z, x4.z, b0); b0 = fmaf(cur[4].w, x4.w, b0);
        b1 = fmaf(cur[5].x, x5.x, b1); b1 = fmaf(cur[5].y, x5.y, b1);
        b1 = fmaf(cur[5].z, x5.z, b1); b1 = fmaf(cur[5].w, x5.w, b1);
        b2 = fmaf(cur[6].x, x6.x, b2); b2 = fmaf(cur[6].y, x6.y, b2);
        b2 = fmaf(cur[6].z, x6.z, b2); b2 = fmaf(cur[6].w, x6.w, b2);
        b3 = fmaf(cur[7].x, x7.x, b3); b3 = fmaf(cur[7].y, x7.y, b3);
        b3 = fmaf(cur[7].z, x7.z, b3); b3 = fmaf(cur[7].w, x7.w, b3);
        r = r - ((b0 + b1) + (b2 + b3));
        #pragma unroll
        for (int u = 0; u < 8; ++u) cur[u] = nxt[u];
    }

    // solve own 32x32 diagonal block (8-col speculative sub-blocks)
    {
        float pc[32];
        #pragma unroll
        for (int u = 0; u < 8; ++u) {
            pc[4*u+0] = cur[u].x; pc[4*u+1] = cur[u].y;
            pc[4*u+2] = cur[u].z; pc[4*u+3] = cur[u].w;
        }
        #pragma unroll
        for (int q = 0; q < 4; ++q) {
            const int base = q * 8;
            const float* tq = &tri[w][q][0];
            float a0 = __shfl_sync(0xFFFFFFFFu, r, base + 0);
            float a1 = __shfl_sync(0xFFFFFFFFu, r, base + 1);
            float a2 = __shfl_sync(0xFFFFFFFFu, r, base + 2);
            float a3 = __shfl_sync(0xFFFFFFFFu, r, base + 3);
            float a4 = __shfl_sync(0xFFFFFFFFu, r, base + 4);
            float a5 = __shfl_sync(0xFFFFFFFFu, r, base + 5);
            float a6 = __shfl_sync(0xFFFFFFFFu, r, base + 6);
            float a7 = __shfl_sync(0xFFFFFFFFu, r, base + 7);
            float v0 = fmaxf(a0, 0.f);
            a1 = fmaf(-tq[0], v0, a1);  float v1 = fmaxf(a1, 0.f);
            a2 = fmaf(-tq[1], v0, a2);  a2 = fmaf(-tq[2], v1, a2);
            float v2 = fmaxf(a2, 0.f);
            a3 = fmaf(-tq[3], v0, a3);  a3 = fmaf(-tq[4], v1, a3);
            a3 = fmaf(-tq[5], v2, a3);  float v3 = fmaxf(a3, 0.f);
            a4 = fmaf(-tq[6], v0, a4);  a4 = fmaf(-tq[7], v1, a4);
            a4 = fmaf(-tq[8], v2, a4);  a4 = fmaf(-tq[9], v3, a4);
            float v4 = fmaxf(a4, 0.f);
            a5 = fmaf(-tq[10], v0, a5); a5 = fmaf(-tq[11], v1, a5);
            a5 = fmaf(-tq[12], v2, a5); a5 = fmaf(-tq[13], v3, a5);
            a5 = fmaf(-tq[14], v4, a5); float v5 = fmaxf(a5, 0.f);
            a6 = fmaf(-tq[15], v0, a6); a6 = fmaf(-tq[16], v1, a6);
            a6 = fmaf(-tq[17], v2, a6); a6 = fmaf(-tq[18], v3, a6);
            a6 = fmaf(-tq[19], v4, a6); a6 = fmaf(-tq[20], v5, a6);
            float v6 = fmaxf(a6, 0.f);
            a7 = fmaf(-tq[21], v0, a7); a7 = fmaf(-tq[22], v1, a7);
            a7 = fmaf(-tq[23], v2, a7); a7 = fmaf(-tq[24], v3, a7);
            a7 = fmaf(-tq[25], v4, a7); a7 = fmaf(-tq[26], v5, a7);
            a7 = fmaf(-tq[27], v6, a7); float v7 = fmaxf(a7, 0.f);
            if (lane == base + 0) vsh[tid] = v0;
            if (lane == base + 1) vsh[tid] = v1;
            if (lane == base + 2) vsh[tid] = v2;
            if (lane == base + 3) vsh[tid] = v3;
            if (lane == base + 4) vsh[tid] = v4;
            if (lane == base + 5) vsh[tid] = v5;
            if (lane == base + 6) vsh[tid] = v6;
            if (lane == base + 7) vsh[tid] = v7;
            float m01 = pc[base + 0] * v0; m01 = fmaf(pc[base + 1], v1, m01);
            float m23 = pc[base + 2] * v2; m23 = fmaf(pc[base + 3], v3, m23);
            float m45 = pc[base + 4] * v4; m45 = fmaf(pc[base + 5], v5, m45);
            float m67 = pc[base + 6] * v6; m67 = fmaf(pc[base + 7], v7, m67);
            r = r - ((m01 + m23) + (m45 + m67));
        }
    }
    __syncwarp();
    __threadfence_block();
    if (lane == 0) flag[w] = 1;

    // epilogue: this warp's rows are final
    float v = vsh[tid];
    float E = __expf(20.f * v);
    bool valid = tid < KSEL;
    g_E[img][tid]  = valid ? E : 0.f;
    g_yE[img][tid] = valid ? g_y[img][tid] * E : 0.f;
}

// ---------------- K5: ap_loss, 32 rows x 4 col-chunks per block ----------------
__global__ __launch_bounds__(128) void k_ap() {
    const int img = blockIdx.y;
    const int rb = blockIdx.x;
    const int c = threadIdx.x >> 5, lane = threadIdx.x & 31;
    const int row = rb * 32 + lane;
    __shared__ float Es[KPAD], yEs[KPAD];
    __shared__ float rsh[4][32], rshy[4][32];
    for (int u = threadIdx.x; u < KPAD; u += 128) {
        Es[u]  = g_E[img][u];
        yEs[u] = g_yE[img][u];
    }
    __syncthreads();
    float Ei = Es[row];
    float sh = 0.f, shy = 0.f;
    const int j0 = c * 125;
    #pragma unroll 5
    for (int j = j0; j < j0 + 125; ++j) {
        float ej = Es[j];
        float rr = frcp(Ei + ej);
        sh  = fmaf(ej, rr, sh);
        shy = fmaf(yEs[j], rr, shy);
    }
    rsh[c][lane] = sh; rshy[c][lane] = shy;
    __syncthreads();
    if (c == 0) {
        float S  = rsh[0][lane] + rsh[1][lane] + rsh[2][lane] + rsh[3][lane];
        float Sy = rshy[0][lane] + rshy[1][lane] + rshy[2][lane] + rshy[3][lane];
        float ci = 0.f;
        float yi = g_y[img][row];
        if (row < KSEL && yi != 0.f)
            ci = __fdividef(0.5f + Sy, 0.5f + S);
        g_c[img][row] = ci;
    }
}

// ---------------- K6: warp-per-image final reduction ----------------
__global__ __launch_bounds__(512) void k_final(float* __restrict__ out) {
    const int w = threadIdx.x >> 5, lane = threadIdx.x & 31;
    __shared__ float part[16];
    float sc = 0.f, sy = 0.f;
    #pragma unroll
    for (int u = lane; u < KPAD; u += 32) {
        sc += g_c[w][u];
        sy += g_y[w][u];
    }
    #pragma unroll
    for (int off = 16; off > 0; off >>= 1) {
        sc += __shfl_down_sync(0xFFFFFFFFu, sc, off);
        sy += __shfl_down_sync(0xFFFFFFFFu, sy, off);
    }
    if (lane == 0) part[w] = 1.f - sc / fmaxf(sy, 1.f);
    __syncthreads();
    if (threadIdx.x == 0) {
        float t = 0.f;
        #pragma unroll
        for (int k = 0; k < NIMG; ++k) t += part[k];
        out[0] = t / (float)NIMG;
    }
}

// ---------------- driver ----------------
extern "C" void kernel_launch(void* const* d_in, const int* in_sizes, int n_in,
                              void* d_out, int out_size) {
    const float* preds = nullptr;
    const float* boxes = nullptr;
    const int*   targets = nullptr;
    for (int i = 0; i < n_in; ++i) {
        long sz = in_sizes[i];
        if (sz == (long)NIMG * NBOX * NCH) preds = (const float*)d_in[i];
        else if (sz == (long)NIMG * NBOX * 4) boxes = (const float*)d_in[i];
        else if (sz == (long)NIMG * NBOX) targets = (const int*)d_in[i];
    }
    if (!preds)   preds   = (const float*)d_in[0];
    if (!boxes)   boxes   = (const float*)d_in[1];
    if (!targets) targets = (const int*)d_in[2];

    k_scores<<<NIMG * 126, 128>>>(preds);
    k_select<<<NIMG, 512>>>(reinterpret_cast<const float4*>(boxes), targets);
    k_prune<<<dim3(34, NIMG), 128>>>();
    k_nms<<<NIMG, 512>>>();
    k_ap<<<dim3(16, NIMG), 128>>>();
    k_final<<<1, 512>>>((float*)d_out);
}

// round 5
// speedup vs baseline: 1.0530x; 1.0374x over previous
#include <cuda_runtime.h>
#include <cuda_bf16.h>
#include <cstdint>

#define NIMG 16
#define NBOX 16128
#define NCH  85
#define KSEL 500
#define KPAD 512
#define NCB  16            // 512 / 32 column blocks
#define SROW 33            // padded row stride (words) in staging buffer
#define SIG_NEG4 0.017986210f   // sigmoid(-4) for zero-overlap pairs

#define BAR_SYNC(id,cnt)   asm volatile("bar.sync %0, %1;"   :: "r"(id), "r"(cnt) : "memory")
#define BAR_ARRIVE(id,cnt) asm volatile("bar.arrive %0, %1;" :: "r"(id), "r"(cnt) : "memory")

// ---------------- device scratch (no allocations allowed) ----------------
__device__ unsigned g_sbits[NIMG * NBOX];                 // packed score bits
__device__ float    g_s[NIMG][KPAD];                      // sorted top scores
__device__ float4   g_box[NIMG][KPAD];                    // gathered boxes
__device__ float    g_y[NIMG][KPAD];                      // gathered targets
__device__ float    g_p[(size_t)NIMG * NCB * KPAD * 32];  // prune, [img][cb][i][t]
__device__ float    g_tri[NIMG][NCB][4][32];              // diag 8x8 triangles
__device__ float    g_E[NIMG][KPAD];                      // exp(20*v)
__device__ float    g_yE[NIMG][KPAD];                     // y * exp(20*v)
__device__ float    g_c[NIMG][KPAD];                      // prec*y per row

__constant__ unsigned char c_tk[28] = {1,2,2,3,3,3,4,4,4,4,5,5,5,5,5,
                                       6,6,6,6,6,6,7,7,7,7,7,7,7};
__constant__ unsigned char c_tj[28] = {0,0,1,0,1,2,0,1,2,3,0,1,2,3,4,
                                       0,1,2,3,4,5,0,1,2,3,4,5,6};

__device__ __forceinline__ float frcp(float x) {
    float r; asm("rcp.approx.f32 %0, %1;" : "=f"(r) : "f"(x)); return r;
}

// ---------------- K1: scores = max over channels 1..84 ----------------
__global__ __launch_bounds__(128) void k_scores(const float* __restrict__ preds) {
    __shared__ __align__(16) float sh[128 * NCH];
    int img = blockIdx.x / 126;
    int ch  = blockIdx.x % 126;
    size_t base = ((size_t)img * NBOX + (size_t)ch * 128) * NCH;
    const float4* src = reinterpret_cast<const float4*>(preds + base);
    float4* dst = reinterpret_cast<float4*>(sh);
    #pragma unroll 8
    for (int u = threadIdx.x; u < 128 * NCH / 4; u += 128) dst[u] = src[u];
    __syncthreads();
    int r = threadIdx.x;
    float m = sh[r * NCH + 1];
    #pragma unroll
    for (int c = 2; c < NCH; ++c) m = fmaxf(m, sh[r * NCH + c]);
    g_sbits[(size_t)img * NBOX + ch * 128 + r] = __float_as_uint(m);
}

// ---------------- K2: per-image radix select (4x8-bit) + bitonic ----------------
__global__ __launch_bounds__(512) void k_select(const float4* __restrict__ boxes,
                                                const int* __restrict__ tgt) {
    const int img = blockIdx.x;
    const int tid = threadIdx.x;
    const int w = tid >> 5, lane = tid & 31;
    __shared__ unsigned whist[16 * 256];
    __shared__ unsigned hist[256];
    __shared__ unsigned wtot[16];
    __shared__ unsigned s_bin, s_rem, s_cnt;
    __shared__ unsigned long long sbuf[1024];
    const unsigned* sb = g_sbits + (size_t)img * NBOX;

    unsigned prefix = 0;
    unsigned target = KSEL;

    #pragma unroll
    for (int pass = 0; pass < 4; ++pass) {
        const int shift = 24 - pass * 8;
        for (int u = tid; u < 4096; u += 512) whist[u] = 0;
        __syncthreads();
        for (int j = tid; j < NBOX; j += 512) {
            unsigned bits = sb[j];
            bool ok = (pass == 0) || ((bits >> (shift + 8)) == prefix);
            unsigned act = __ballot_sync(0xFFFFFFFFu, ok);
            if (ok) {
                unsigned bin = (bits >> shift) & 255u;
                unsigned mask = __match_any_sync(act, bin);
                if ((mask & ((1u << lane) - 1u)) == 0)
                    whist[w * 256 + bin] += __popc(mask);
            }
        }
        __syncthreads();
        if (tid < 256) {
            unsigned h = 0;
            #pragma unroll
            for (int ww = 0; ww < 16; ++ww) h += whist[ww * 256 + tid];
            hist[tid] = h;
        }
        __syncthreads();
        unsigned x0 = (tid < 256) ? hist[255 - tid] : 0u;
        unsigned x = x0;
        #pragma unroll
        for (int off = 1; off < 32; off <<= 1) {
            unsigned yv = __shfl_up_sync(0xFFFFFFFFu, x, off);
            if (lane >= off) x += yv;
        }
        if (lane == 31) wtot[w] = x;
        __syncthreads();
        unsigned add = 0;
        #pragma unroll
        for (int ww = 0; ww < 8; ++ww) if (ww < w) add += wtot[ww];
        unsigned inc = x + add;
        if (tid < 256 && inc >= target && (inc - x0) < target) {
            s_bin = 255u - (unsigned)tid;
            s_rem = target - (inc - x0);
        }
        __syncthreads();
        prefix = (prefix << 8) | s_bin;
        target = s_rem;
        __syncthreads();
    }
    const unsigned T = prefix;

    for (int u = tid; u < 1024; u += 512) sbuf[u] = ~0ULL;
    if (tid == 0) s_cnt = 0;
    __syncthreads();
    for (int j = tid; j < NBOX; j += 512) {
        unsigned bits = sb[j];
        if (bits >= T) {
            unsigned p = atomicAdd(&s_cnt, 1);
            if (p < 1024)
                sbuf[p] = ~(((unsigned long long)bits << 32) |
                            (unsigned long long)(0xFFFFFFFFu - (unsigned)j));
        }
    }
    __syncthreads();

    for (unsigned kk = 2; kk <= 1024; kk <<= 1) {
        for (unsigned st = kk >> 1; st > 0; st >>= 1) {
            unsigned t = (unsigned)tid;
            unsigned i = ((t & ~(st - 1)) << 1) | (t & (st - 1));
            unsigned j2 = i | st;
            bool up = ((i & kk) == 0);
            unsigned long long a = sbuf[i], b = sbuf[j2];
            if ((a > b) == up) { sbuf[i] = b; sbuf[j2] = a; }
            __syncthreads();
        }
    }

    if (tid < KSEL) {
        unsigned long long key = ~sbuf[tid];
        unsigned bits = (unsigned)(key >> 32);
        unsigned idx  = 0xFFFFFFFFu - (unsigned)(key & 0xFFFFFFFFull);
        g_s[img][tid] = __uint_as_float(bits);
        g_box[img][tid] = boxes[(size_t)img * NBOX + idx];
        g_y[img][tid] = (float)tgt[(size_t)img * NBOX + idx];
    } else {
        g_s[img][tid] = 0.f;
        g_box[img][tid] = make_float4(0.f, 0.f, 0.f, 0.f);
        g_y[img][tid] = 0.f;
    }
}

// ---------------- K3: prune matrix, triangle tiles only ----------------
__global__ __launch_bounds__(128) void k_prune() {
    const int img = blockIdx.y;
    const int w = threadIdx.x >> 5, lane = threadIdx.x & 31;
    const int t = blockIdx.x * 4 + w;                 // tile id, 0..135
    __shared__ float4 sbj[4][32];
    __shared__ float  saj[4][32];
    __shared__ float  sdiag[4][32][32];

    int rb = (int)((sqrtf(8.f * (float)t + 1.f) - 1.f) * 0.5f);
    if ((rb + 1) * (rb + 2) / 2 <= t) rb++;
    if (rb * (rb + 1) / 2 > t) rb--;
    const int cb = t - rb * (rb + 1) / 2;

    {
        float4 b = g_box[img][cb * 32 + lane];
        sbj[w][lane] = b;
        saj[w][lane] = fmaxf(b.z - b.x, 0.f) * fmaxf(b.w - b.y, 0.f);
    }
    __syncwarp();

    const int i = rb * 32 + lane;
    float4 bi = g_box[img][i];
    float ai = fmaxf(bi.z - bi.x, 0.f) * fmaxf(bi.w - bi.y, 0.f);
    float out[32];
    #pragma unroll
    for (int c = 0; c < 32; ++c) {
        float4 bb = sbj[w][c];
        float iw = fminf(bi.z, bb.z) - fmaxf(bi.x, bb.x);
        float ih = fminf(bi.w, bb.w) - fmaxf(bi.y, bb.y);
        bool ov = (iw > 0.f) && (ih > 0.f);
        float p;
        if (__any_sync(0xFFFFFFFFu, ov)) {
            float inter = fmaxf(iw, 0.f) * fmaxf(ih, 0.f);
            float uni = ai + saj[w][c] - inter;
            float iou = inter * frcp(fmaxf(uni, 1e-9f));
            p = frcp(1.f + __expf((0.4f - iou) * 10.f));
        } else {
            p = SIG_NEG4;
        }
        out[c] = p;
    }
    float4* dst = reinterpret_cast<float4*>(
        &g_p[(((size_t)img * NCB + cb) * KPAD + i) * 32]);
    #pragma unroll
    for (int u = 0; u < 8; ++u) dst[u] = reinterpret_cast<float4*>(out)[u];

    if (rb == cb) {
        #pragma unroll
        for (int c = 0; c < 32; ++c) sdiag[w][lane][c] = out[c];
        __syncwarp();
        for (int e = lane; e < 112; e += 32) {
            int q = e / 28, rem = e - q * 28;
            int k = c_tk[rem], j = c_tj[rem];
            g_tri[img][cb][q][rem] = sdiag[w][q * 8 + k][q * 8 + j];
        }
    }
}

// ---------------- K4: soft-NMS — coalesced tiles + named-barrier pipeline ----------------
extern __shared__ float sdyn[];     // 16 warps x 32x33 staging = 67584 B

__global__ __launch_bounds__(512) void k_nms() {
    const int img = blockIdx.x;
    const int tid = threadIdx.x;
    const int w = tid >> 5, lane = tid & 31;
    __shared__ __align__(16) float vsh[KPAD];
    __shared__ float tri[NCB][4][32];
    float* sbuf = &sdyn[w * (32 * SROW)];

    for (int u = tid; u < NCB * 4 * 32; u += 512)
        reinterpret_cast<float*>(tri)[u] =
            reinterpret_cast<const float*>(g_tri)[img * (NCB * 4 * 32) + u];

    float r = g_s[img][tid];
    __syncthreads();                      // tri + vsh init visibility

    // stage tile 0 (coalesced 4KB load -> shared transpose)
    {
        const float4* tb = reinterpret_cast<const float4*>(g_p) +
                           (((size_t)img * NCB + 0) * KPAD + 32 * w) * 8;
        float4 L[8];
        #pragma unroll
        for (int u = 0; u < 8; ++u) L[u] = tb[u * 32 + lane];
        #pragma unroll
        for (int u = 0; u < 8; ++u) {
            int c = u * 32 + lane;
            float* d = &sbuf[(c >> 3) * SROW + (c & 7) * 4];
            d[0] = L[u].x; d[1] = L[u].y; d[2] = L[u].z; d[3] = L[u].w;
        }
        __syncwarp();
    }

    const float* prow = &sbuf[lane * SROW];

    // consume column blocks 0..w-1 (pipelined with next-tile load)
    for (int cb = 0; cb < w; ++cb) {
        const float4* tb = reinterpret_cast<const float4*>(g_p) +
                           (((size_t)img * NCB + (cb + 1)) * KPAD + 32 * w) * 8;
        float4 L[8];
        #pragma unroll
        for (int u = 0; u < 8; ++u) L[u] = tb[u * 32 + lane];

        BAR_SYNC(cb, (NCB - cb) * 32);    // wait for v[cb*32 .. +31]

        const float* vv = &vsh[cb * 32];
        float a0 = 0.f, a1 = 0.f, a2 = 0.f, a3 = 0.f;
        #pragma unroll
        for (int j = 0; j < 32; j += 4) {
            a0 = fmaf(prow[j + 0], vv[j + 0], a0);
            a1 = fmaf(prow[j + 1], vv[j + 1], a1);
            a2 = fmaf(prow[j + 2], vv[j + 2], a2);
            a3 = fmaf(prow[j + 3], vv[j + 3], a3);
        }
        r = r - ((a0 + a1) + (a2 + a3));

        #pragma unroll
        for (int u = 0; u < 8; ++u) {
            int c = u * 32 + lane;
            float* d = &sbuf[(c >> 3) * SROW + (c & 7) * 4];
            d[0] = L[u].x; d[1] = L[u].y; d[2] = L[u].z; d[3] = L[u].w;
        }
        __syncwarp();
    }

    // solve own 32x32 diagonal block (8-col speculative sub-blocks)
    #pragma unroll
    for (int q = 0; q < 4; ++q) {
        const int base = q * 8;
        const float* tq = &tri[w][q][0];
        float a0 = __shfl_sync(0xFFFFFFFFu, r, base + 0);
        float a1 = __shfl_sync(0xFFFFFFFFu, r, base + 1);
        float a2 = __shfl_sync(0xFFFFFFFFu, r, base + 2);
        float a3 = __shfl_sync(0xFFFFFFFFu, r, base + 3);
        float a4 = __shfl_sync(0xFFFFFFFFu, r, base + 4);
        float a5 = __shfl_sync(0xFFFFFFFFu, r, base + 5);
        float a6 = __shfl_sync(0xFFFFFFFFu, r, base + 6);
        float a7 = __shfl_sync(0xFFFFFFFFu, r, base + 7);
        float v0 = fmaxf(a0, 0.f);
        a1 = fmaf(-tq[0], v0, a1);  float v1 = fmaxf(a1, 0.f);
        a2 = fmaf(-tq[1], v0, a2);  a2 = fmaf(-tq[2], v1, a2);
        float v2 = fmaxf(a2, 0.f);
        a3 = fmaf(-tq[3], v0, a3);  a3 = fmaf(-tq[4], v1, a3);
        a3 = fmaf(-tq[5], v2, a3);  float v3 = fmaxf(a3, 0.f);
        a4 = fmaf(-tq[6], v0, a4);  a4 = fmaf(-tq[7], v1, a4);
        a4 = fmaf(-tq[8], v2, a4);  a4 = fmaf(-tq[9], v3, a4);
        float v4 = fmaxf(a4, 0.f);
        a5 = fmaf(-tq[10], v0, a5); a5 = fmaf(-tq[11], v1, a5);
        a5 = fmaf(-tq[12], v2, a5); a5 = fmaf(-tq[13], v3, a5);
        a5 = fmaf(-tq[14], v4, a5); float v5 = fmaxf(a5, 0.f);
        a6 = fmaf(-tq[15], v0, a6); a6 = fmaf(-tq[16], v1, a6);
        a6 = fmaf(-tq[17], v2, a6); a6 = fmaf(-tq[18], v3, a6);
        a6 = fmaf(-tq[19], v4, a6); a6 = fmaf(-tq[20], v5, a6);
        float v6 = fmaxf(a6, 0.f);
        a7 = fmaf(-tq[21], v0, a7); a7 = fmaf(-tq[22], v1, a7);
        a7 = fmaf(-tq[23], v2, a7); a7 = fmaf(-tq[24], v3, a7);
        a7 = fmaf(-tq[25], v4, a7); a7 = fmaf(-tq[26], v5, a7);
        a7 = fmaf(-tq[27], v6, a7); float v7 = fmaxf(a7, 0.f);
        if (lane == base + 0) vsh[tid] = v0;
        if (lane == base + 1) vsh[tid] = v1;
        if (lane == base + 2) vsh[tid] = v2;
        if (lane == base + 3) vsh[tid] = v3;
        if (lane == base + 4) vsh[tid] = v4;
        if (lane == base + 5) vsh[tid] = v5;
        if (lane == base + 6) vsh[tid] = v6;
        if (lane == base + 7) vsh[tid] = v7;
        float m01 = prow[base + 0] * v0; m01 = fmaf(prow[base + 1], v1, m01);
        float m23 = prow[base + 2] * v2; m23 = fmaf(prow[base + 3], v3, m23);
        float m45 = prow[base + 4] * v4; m45 = fmaf(prow[base + 5], v5, m45);
        float m67 = prow[base + 6] * v6; m67 = fmaf(prow[base + 7], v7, m67);
        r = r - ((m01 + m23) + (m45 + m67));
    }
    __syncwarp();
    __threadfence_block();
    if (w < NCB - 1) BAR_ARRIVE(w, (NCB - w) * 32);   // publish v's to later warps

    // epilogue: this warp's rows are final
    float v = vsh[tid];
    float E = __expf(20.f * v);
    bool valid = tid < KSEL;
    g_E[img][tid]  = valid ? E : 0.f;
    g_yE[img][tid] = valid ? g_y[img][tid] * E : 0.f;
}

// ---------------- K5: ap_loss, 32 rows x 4 col-chunks per block ----------------
__global__ __launch_bounds__(128) void k_ap() {
    const int img = blockIdx.y;
    const int rb = blockIdx.x;
    const int c = threadIdx.x >> 5, lane = threadIdx.x & 31;
    const int row = rb * 32 + lane;
    __shared__ float Es[KPAD], yEs[KPAD];
    __shared__ float rsh[4][32], rshy[4][32];
    for (int u = threadIdx.x; u < KPAD; u += 128) {
        Es[u]  = g_E[img][u];
        yEs[u] = g_yE[img][u];
    }
    __syncthreads();
    float Ei = Es[row];
    float sh = 0.f, shy = 0.f;
    const int j0 = c * 125;
    #pragma unroll 5
    for (int j = j0; j < j0 + 125; ++j) {
        float ej = Es[j];
        float rr = frcp(Ei + ej);
        sh  = fmaf(ej, rr, sh);
        shy = fmaf(yEs[j], rr, shy);
    }
    rsh[c][lane] = sh; rshy[c][lane] = shy;
    __syncthreads();
    if (c == 0) {
        float S  = rsh[0][lane] + rsh[1][lane] + rsh[2][lane] + rsh[3][lane];
        float Sy = rshy[0][lane] + rshy[1][lane] + rshy[2][lane] + rshy[3][lane];
        float ci = 0.f;
        float yi = g_y[img][row];
        if (row < KSEL && yi != 0.f)
            ci = __fdividef(0.5f + Sy, 0.5f + S);
        g_c[img][row] = ci;
    }
}

// ---------------- K6: warp-per-image final reduction ----------------
__global__ __launch_bounds__(512) void k_final(float* __restrict__ out) {
    const int w = threadIdx.x >> 5, lane = threadIdx.x & 31;
    __shared__ float part[16];
    float sc = 0.f, sy = 0.f;
    #pragma unroll
    for (int u = lane; u < KPAD; u += 32) {
        sc += g_c[w][u];
        sy += g_y[w][u];
    }
    #pragma unroll
    for (int off = 16; off > 0; off >>= 1) {
        sc += __shfl_down_sync(0xFFFFFFFFu, sc, off);
        sy += __shfl_down_sync(0xFFFFFFFFu, sy, off);
    }
    if (lane == 0) part[w] = 1.f - sc / fmaxf(sy, 1.f);
    __syncthreads();
    if (threadIdx.x == 0) {
        float t = 0.f;
        #pragma unroll
        for (int k = 0; k < NIMG; ++k) t += part[k];
        out[0] = t / (float)NIMG;
    }
}

// ---------------- driver ----------------
extern "C" void kernel_launch(void* const* d_in, const int* in_sizes, int n_in,
                              void* d_out, int out_size) {
    const float* preds = nullptr;
    const float* boxes = nullptr;
    const int*   targets = nullptr;
    for (int i = 0; i < n_in; ++i) {
        long sz = in_sizes[i];
        if (sz == (long)NIMG * NBOX * NCH) preds = (const float*)d_in[i];
        else if (sz == (long)NIMG * NBOX * 4) boxes = (const float*)d_in[i];
        else if (sz == (long)NIMG * NBOX) targets = (const int*)d_in[i];
    }
    if (!preds)   preds   = (const float*)d_in[0];
    if (!boxes)   boxes   = (const float*)d_in[1];
    if (!targets) targets = (const int*)d_in[2];

    const int nms_smem = NCB * 32 * SROW * (int)sizeof(float);   // 67584 B
    cudaFuncSetAttribute(k_nms, cudaFuncAttributeMaxDynamicSharedMemorySize, nms_smem);

    k_scores<<<NIMG * 126, 128>>>(preds);
    k_select<<<NIMG, 512>>>(reinterpret_cast<const float4*>(boxes), targets);
    k_prune<<<dim3(34, NIMG), 128>>>();
    k_nms<<<NIMG, 512, nms_smem>>>();
    k_ap<<<dim3(16, NIMG), 128>>>();
    k_final<<<1, 512>>>((float*)d_out);
}